// round 6
// baseline (speedup 1.0000x reference)
#include <cuda_runtime.h>
#include <cuda_bf16.h>
#include <cstdint>

#define NN     50000
#define EE     800000
#define EI     200000
#define HH     4
#define DD     32
#define SLOPE  0.2f

// ---- scratch layout inside d_out (floats) ------------------------------------
// d_out total = NN*128 + EI*256 = 6,400,000 + 51,200,000 = 57,600,000 floats.
// Final h lives at [0, 6.4M). The edges region [6.4M, 57.6M) is only written by
// the LAST kernel, so its front serves as scratch for the two GAT layers:
#define S_FT    6400000     //  6.4M floats  (projected features, per layer)
#define S_MSG  12800000     //  6.4M floats  (message accumulator)
#define S_H1   19200000     //  6.4M floats  (layer-1 output)
#define S_EL   25600000     //  0.2M
#define S_ER   25800000     //  0.2M
#define S_DEN  26000000     //  0.2M   (end 26.2M < 57.6M, OK)

// =================================================================================
// Kernel 1: ft = X @ W  (N x 128 @ 128 x 128), fused el/er and msg/denom zero-init.
// 256 threads, tile = 64 rows x 128 cols, micro-tile 8x4 per thread.
// smem: W full (64KB) + X tile transposed with pad (128*68 f32).
// =================================================================================
__global__ void __launch_bounds__(256, 1)
gat_gemm_kernel(const float* __restrict__ X, const float* __restrict__ W,
                const float* __restrict__ al, const float* __restrict__ ar,
                float* __restrict__ ft, float* __restrict__ msg,
                float* __restrict__ el, float* __restrict__ er,
                float* __restrict__ den)
{
    extern __shared__ float smem[];
    float* Ws = smem;            // [128][128]
    float* Xs = smem + 16384;    // [128][68]  (xT[k*68 + r], pad 68 avoids conflicts)

    const int t    = threadIdx.x;
    const int lane = t & 31;
    const int warp = t >> 5;
    const int c0   = lane * 4;   // 4 output columns
    const int r0   = warp * 8;   // 8 rows within the tile
    const int row0 = blockIdx.x * 64;

    {
        const float4* W4 = reinterpret_cast<const float4*>(W);
        float4* Ws4 = reinterpret_cast<float4*>(Ws);
        #pragma unroll
        for (int i = t; i < 4096; i += 256) Ws4[i] = W4[i];
    }
    const float4 alv = reinterpret_cast<const float4*>(al)[lane];
    const float4 arv = reinterpret_cast<const float4*>(ar)[lane];

    for (int i = t; i < 64 * 128; i += 256) {
        int r = i >> 7, k = i & 127;
        int row = row0 + r;
        Xs[k * 68 + r] = (row < NN) ? X[(size_t)row * 128 + k] : 0.f;
    }
    __syncthreads();

    float acc[8][4];
    #pragma unroll
    for (int r = 0; r < 8; r++)
        #pragma unroll
        for (int c = 0; c < 4; c++) acc[r][c] = 0.f;

    #pragma unroll 4
    for (int k = 0; k < 128; k++) {
        float4 w  = *reinterpret_cast<const float4*>(&Ws[k * 128 + c0]);
        float4 x0 = *reinterpret_cast<const float4*>(&Xs[k * 68 + r0]);
        float4 x1 = *reinterpret_cast<const float4*>(&Xs[k * 68 + r0 + 4]);
        float xs[8] = {x0.x, x0.y, x0.z, x0.w, x1.x, x1.y, x1.z, x1.w};
        #pragma unroll
        for (int r = 0; r < 8; r++) {
            acc[r][0] += xs[r] * w.x;
            acc[r][1] += xs[r] * w.y;
            acc[r][2] += xs[r] * w.z;
            acc[r][3] += xs[r] * w.w;
        }
    }

    const float4 zero4 = make_float4(0.f, 0.f, 0.f, 0.f);
    #pragma unroll
    for (int r = 0; r < 8; r++) {
        int row = row0 + r0 + r;
        float pe = acc[r][0]*alv.x + acc[r][1]*alv.y + acc[r][2]*alv.z + acc[r][3]*alv.w;
        float pr = acc[r][0]*arv.x + acc[r][1]*arv.y + acc[r][2]*arv.z + acc[r][3]*arv.w;
        // reduce within 8-lane head groups (head = lane>>3, since D=32 -> 8 lanes/head)
        pe += __shfl_down_sync(0xffffffffu, pe, 4, 8);
        pe += __shfl_down_sync(0xffffffffu, pe, 2, 8);
        pe += __shfl_down_sync(0xffffffffu, pe, 1, 8);
        pr += __shfl_down_sync(0xffffffffu, pr, 4, 8);
        pr += __shfl_down_sync(0xffffffffu, pr, 2, 8);
        pr += __shfl_down_sync(0xffffffffu, pr, 1, 8);
        if (row < NN) {
            float4 a4 = make_float4(acc[r][0], acc[r][1], acc[r][2], acc[r][3]);
            *reinterpret_cast<float4*>(&ft [(size_t)row * 128 + c0]) = a4;
            *reinterpret_cast<float4*>(&msg[(size_t)row * 128 + c0]) = zero4;
            if ((lane & 7) == 0) {
                int h = lane >> 3;
                el[(size_t)row * 4 + h] = pe;
                er[(size_t)row * 4 + h] = pr;
            }
            if (lane < 4) den[(size_t)row * 4 + lane] = 0.f;
        }
    }
}

// =================================================================================
// Kernel 2: edge aggregation. One warp per edge.
//   a[h] = exp(leaky_relu(el[s,h] + er[d,h]))   (max-shift dropped: |e| <~ 3.5,
//                                                ratio a/denom mathematically same)
//   den[d,h] += a[h];   msg[d,:] += a[h] * ft[s,:]
// =================================================================================
__global__ void __launch_bounds__(256, 8)
gat_edge_kernel(const int* __restrict__ src, const int* __restrict__ dst,
                const float* __restrict__ ft, float* __restrict__ msg,
                const float* __restrict__ el, const float* __restrict__ er,
                float* __restrict__ den)
{
    int e = (blockIdx.x * blockDim.x + threadIdx.x) >> 5;
    if (e >= EE) return;
    int lane = threadIdx.x & 31;

    int s = __ldg(&src[e]);
    int d = __ldg(&dst[e]);

    float a = 0.f;
    if (lane < 4) {
        float v = el[(size_t)s * 4 + lane] + er[(size_t)d * 4 + lane];
        v = (v > 0.f) ? v : SLOPE * v;
        a = __expf(v);
        atomicAdd(&den[(size_t)d * 4 + lane], a);
    }
    float ah = __shfl_sync(0xffffffffu, a, lane >> 3);   // head = lane/8

    float4 f = reinterpret_cast<const float4*>(ft)[(size_t)s * 32 + lane];

    float* mp = &msg[(size_t)d * 128 + lane * 4];
    asm volatile("red.global.add.v4.f32 [%0], {%1,%2,%3,%4};"
                 :: "l"(mp), "f"(ah * f.x), "f"(ah * f.y),
                    "f"(ah * f.z), "f"(ah * f.w)
                 : "memory");
}

// =================================================================================
// Kernel 3: out = elu(msg / max(den, 1e-9)). One thread per float4.
// =================================================================================
__device__ __forceinline__ float elu1(float x) {
    return (x > 0.f) ? x : expm1f(x);
}

__global__ void gat_norm_kernel(const float* __restrict__ msg,
                                const float* __restrict__ den,
                                float* __restrict__ out)
{
    int idx = blockIdx.x * blockDim.x + threadIdx.x;
    if (idx >= NN * 32) return;
    int i = idx >> 5, q = idx & 31, h = q >> 3;
    float inv = 1.0f / fmaxf(den[(size_t)i * 4 + h], 1e-9f);
    float4 m = reinterpret_cast<const float4*>(msg)[idx];
    float4 r;
    r.x = elu1(m.x * inv);
    r.y = elu1(m.y * inv);
    r.z = elu1(m.z * inv);
    r.w = elu1(m.w * inv);
    reinterpret_cast<float4*>(out)[idx] = r;
}

// =================================================================================
// Kernel 4: edge features. out[p, h*64 + 0..31] = hf[i0,h,:], [32..63] = hf[i1,h,:]
// One thread per output float4 (64 float4 per pair).
// =================================================================================
__global__ void gat_edgefeat_kernel(const float* __restrict__ hf,
                                    const int* __restrict__ ind0,
                                    const int* __restrict__ ind1,
                                    float* __restrict__ out)
{
    int idx = blockIdx.x * blockDim.x + threadIdx.x;
    if (idx >= EI * 64) return;
    int p = idx >> 6;
    int q = idx & 63;           // float4 index within 256-float row
    int h = q >> 4;             // 16 float4 per head block
    int w = q & 15;
    int node = (w < 8) ? __ldg(&ind0[p]) : __ldg(&ind1[p]);
    float4 v = reinterpret_cast<const float4*>(hf)[(size_t)node * 32 + h * 8 + (w & 7)];
    reinterpret_cast<float4*>(out)[(size_t)p * 64 + q] = v;
}

// =================================================================================
// Launch
// =================================================================================
extern "C" void kernel_launch(void* const* d_in, const int* in_sizes, int n_in,
                              void* d_out, int out_size)
{
    const float* x      = (const float*)d_in[0];
    const int*   src    = (const int*)  d_in[1];
    const int*   dst    = (const int*)  d_in[2];
    const int*   indics = (const int*)  d_in[3];
    const float* W0     = (const float*)d_in[4];
    const float* al0    = (const float*)d_in[5];
    const float* ar0    = (const float*)d_in[6];
    const float* W1     = (const float*)d_in[7];
    const float* al1    = (const float*)d_in[8];
    const float* ar1    = (const float*)d_in[9];

    float* o      = (float*)d_out;
    float* h_out  = o;                       // [N, 128]
    float* edges  = o + (size_t)NN * 128;    // [E_IND, 256] (written LAST)

    // scratch carved out of the edges region (all reads/writes precede edgefeat)
    float* ft  = o + S_FT;
    float* msg = o + S_MSG;
    float* h1  = o + S_H1;
    float* el  = o + S_EL;
    float* er  = o + S_ER;
    float* den = o + S_DEN;

    const int gemm_smem = (16384 + 128 * 68) * 4;       // 100352 bytes
    static int attr_done = 0;
    if (!attr_done) {
        cudaFuncSetAttribute(gat_gemm_kernel,
                             cudaFuncAttributeMaxDynamicSharedMemorySize, gemm_smem);
        attr_done = 1;
    }

    const int gemm_grid = (NN + 63) / 64;
    const int edge_grid = (EE * 32 + 255) / 256;
    const int norm_grid = (NN * 32 + 255) / 256;
    const int ef_grid   = (EI * 64 + 255) / 256;

    // ---- layer 1 ----
    gat_gemm_kernel<<<gemm_grid, 256, gemm_smem>>>(x, W0, al0, ar0, ft, msg, el, er, den);
    gat_edge_kernel<<<edge_grid, 256>>>(src, dst, ft, msg, el, er, den);
    gat_norm_kernel<<<norm_grid, 256>>>(msg, den, h1);

    // ---- layer 2 ----
    gat_gemm_kernel<<<gemm_grid, 256, gemm_smem>>>(h1, W1, al1, ar1, ft, msg, el, er, den);
    gat_edge_kernel<<<edge_grid, 256>>>(src, dst, ft, msg, el, er, den);
    gat_norm_kernel<<<norm_grid, 256>>>(msg, den, h_out);

    // ---- edge features (overwrites the scratch region with the real output) ----
    gat_edgefeat_kernel<<<ef_grid, 256>>>(h_out, indics, indics + EI, edges);
}

// round 7
// speedup vs baseline: 1.1963x; 1.1963x over previous
#include <cuda_runtime.h>
#include <cuda_bf16.h>
#include <cstdint>

#define NN     50000
#define EE     800000
#define EI     200000
#define SLOPE  0.2f

// ---- scratch layout inside d_out (float offsets) -------------------------------
// d_out = NN*128 + EI*256 = 57,600,000 floats. h lives at [0, 6.4M).
// The edges region [6.4M, 57.6M) is written only by the LAST kernel, so its
// front is scratch for everything else:
#define S_FT    6400000u     // 6.4M floats : projected features (per layer)
#define S_H1   12800000u     // 6.4M floats : layer-1 output
#define S_EL   19200000u     // 0.2M
#define S_ER   19400000u     // 0.2M
#define S_OFF  19600000u     // NN+1 ints  : CSR row offsets
#define S_CUR  19800000u     // NN   ints  : counts, then running cursors
#define S_EIDX 20000000u     // EE   ints  : src id per CSR slot (ends 20.8M)

// ---------------- packed f32x2 helpers (Blackwell FFMA2) ------------------------
__device__ __forceinline__ unsigned long long pk2(float lo, float hi) {
    unsigned long long r;
    asm("mov.b64 %0, {%1, %2};" : "=l"(r) : "f"(lo), "f"(hi));
    return r;
}
__device__ __forceinline__ void ffma2(unsigned long long& d,
                                      unsigned long long a, unsigned long long b) {
    asm("fma.rn.f32x2 %0, %1, %2, %0;" : "+l"(d) : "l"(a), "l"(b));
}
__device__ __forceinline__ float2 up2(unsigned long long v) {
    float2 f;
    asm("mov.b64 {%0, %1}, %2;" : "=f"(f.x), "=f"(f.y) : "l"(v));
    return f;
}

// =================================================================================
// GEMM: ft = X @ W (N x 128 @ 128 x 128), fused el/er. 512 threads, 128-row tile,
// micro-tile 8 rows x 4 cols per thread, inner loop on packed f32x2 FMAs.
// smem: W (64KB) + X tile transposed, pad 132 (133,120 B total).
// =================================================================================
#define XPAD 132
__global__ void __launch_bounds__(512, 1)
gat_gemm_kernel(const float* __restrict__ X, const float* __restrict__ W,
                const float* __restrict__ al, const float* __restrict__ ar,
                float* __restrict__ ft, float* __restrict__ el,
                float* __restrict__ er)
{
    extern __shared__ float smem[];
    float* Ws = smem;             // [128][128]
    float* Xs = smem + 16384;     // [128][XPAD]  Xs[k*XPAD + r]

    const int t    = threadIdx.x;
    const int lane = t & 31;
    const int warp = t >> 5;      // 0..15
    const int c0   = lane * 4;
    const int r0   = warp * 8;
    const int row0 = blockIdx.x * 128;

    {
        const float4* W4 = reinterpret_cast<const float4*>(W);
        float4* Ws4 = reinterpret_cast<float4*>(Ws);
        #pragma unroll
        for (int i = t; i < 4096; i += 512) Ws4[i] = W4[i];
    }
    const float4 alv = reinterpret_cast<const float4*>(al)[lane];
    const float4 arv = reinterpret_cast<const float4*>(ar)[lane];

    for (int i = t; i < 128 * 128; i += 512) {
        int r = i >> 7, k = i & 127;
        int row = row0 + r;
        Xs[k * XPAD + r] = (row < NN) ? X[(size_t)row * 128 + k] : 0.f;
    }
    __syncthreads();

    // acc[rp][c] packs rows (2rp, 2rp+1) of column c0+c
    unsigned long long acc[4][4];
    #pragma unroll
    for (int rp = 0; rp < 4; rp++)
        #pragma unroll
        for (int c = 0; c < 4; c++) acc[rp][c] = 0ull;

    #pragma unroll 4
    for (int k = 0; k < 128; k++) {
        float4 w  = *reinterpret_cast<const float4*>(&Ws[k * 128 + c0]);
        float4 x0 = *reinterpret_cast<const float4*>(&Xs[k * XPAD + r0]);
        float4 x1 = *reinterpret_cast<const float4*>(&Xs[k * XPAD + r0 + 4]);
        unsigned long long ww[4] = {pk2(w.x, w.x), pk2(w.y, w.y),
                                    pk2(w.z, w.z), pk2(w.w, w.w)};
        unsigned long long xp[4] = {pk2(x0.x, x0.y), pk2(x0.z, x0.w),
                                    pk2(x1.x, x1.y), pk2(x1.z, x1.w)};
        #pragma unroll
        for (int rp = 0; rp < 4; rp++) {
            ffma2(acc[rp][0], xp[rp], ww[0]);
            ffma2(acc[rp][1], xp[rp], ww[1]);
            ffma2(acc[rp][2], xp[rp], ww[2]);
            ffma2(acc[rp][3], xp[rp], ww[3]);
        }
    }

    #pragma unroll
    for (int r = 0; r < 8; r++) {
        int rp = r >> 1, hl = r & 1;
        float v0 = hl ? up2(acc[rp][0]).y : up2(acc[rp][0]).x;
        float v1 = hl ? up2(acc[rp][1]).y : up2(acc[rp][1]).x;
        float v2 = hl ? up2(acc[rp][2]).y : up2(acc[rp][2]).x;
        float v3 = hl ? up2(acc[rp][3]).y : up2(acc[rp][3]).x;
        int row = row0 + r0 + r;
        float pe = v0*alv.x + v1*alv.y + v2*alv.z + v3*alv.w;
        float pr = v0*arv.x + v1*arv.y + v2*arv.z + v3*arv.w;
        pe += __shfl_down_sync(0xffffffffu, pe, 4, 8);
        pe += __shfl_down_sync(0xffffffffu, pe, 2, 8);
        pe += __shfl_down_sync(0xffffffffu, pe, 1, 8);
        pr += __shfl_down_sync(0xffffffffu, pr, 4, 8);
        pr += __shfl_down_sync(0xffffffffu, pr, 2, 8);
        pr += __shfl_down_sync(0xffffffffu, pr, 1, 8);
        if (row < NN) {
            *reinterpret_cast<float4*>(&ft[(size_t)row * 128 + c0]) =
                make_float4(v0, v1, v2, v3);
            if ((lane & 7) == 0) {
                int h = lane >> 3;
                el[(size_t)row * 4 + h] = pe;
                er[(size_t)row * 4 + h] = pr;
            }
        }
    }
}

// =================================================================================
// CSR build (once per call; reused by both layers — same graph)
// =================================================================================
__global__ void hist_kernel(const int* __restrict__ dst, int* __restrict__ cnt)
{
    int e = blockIdx.x * blockDim.x + threadIdx.x;
    if (e < EE) atomicAdd(&cnt[dst[e]], 1);
}

__global__ void __launch_bounds__(1024, 1)
scan_kernel(int* __restrict__ cntcur, int* __restrict__ off)
{
    __shared__ int ssum[1024];
    const int t = threadIdx.x;
    const int C = (NN + 1023) / 1024;                 // 49
    int lo = t * C, hi = min(lo + C, NN);
    int s = 0;
    for (int i = lo; i < hi; i++) s += cntcur[i];
    ssum[t] = s;
    __syncthreads();
    // inclusive Hillis-Steele scan
    for (int d = 1; d < 1024; d <<= 1) {
        int v = (t >= d) ? ssum[t - d] : 0;
        __syncthreads();
        ssum[t] += v;
        __syncthreads();
    }
    int run = (t > 0) ? ssum[t - 1] : 0;              // exclusive base
    for (int i = lo; i < hi; i++) {
        int c = cntcur[i];
        off[i] = run;
        cntcur[i] = run;                              // becomes scatter cursor
        run += c;
    }
    if (t == 1023) off[NN] = ssum[1023];
}

__global__ void scatter_kernel(const int* __restrict__ src, const int* __restrict__ dst,
                               int* __restrict__ cur, int* __restrict__ eidx)
{
    int e = blockIdx.x * blockDim.x + threadIdx.x;
    if (e >= EE) return;
    int pos = atomicAdd(&cur[dst[e]], 1);
    eidx[pos] = src[e];
}

// =================================================================================
// Gather aggregation + fused normalize + ELU. One warp per dst node.
//   a = exp(leaky_relu(el[s,h] + er[d,h]))  (max-shift dropped; |e| small, ratio
//                                            identical — validated in R5/R6)
//   out[d] = elu( sum_e a*ft[s] / max(sum_e a, 1e-9) )
// =================================================================================
__device__ __forceinline__ float elu1(float x) { return (x > 0.f) ? x : expm1f(x); }

__global__ void __launch_bounds__(256, 8)
gat_aggregate_kernel(const int* __restrict__ off, const int* __restrict__ eidx,
                     const float* __restrict__ ft, const float* __restrict__ el,
                     const float* __restrict__ er, float* __restrict__ out)
{
    int d = (blockIdx.x * blockDim.x + threadIdx.x) >> 5;
    if (d >= NN) return;
    int lane = threadIdx.x & 31;

    float erv = (lane < 4) ? er[(size_t)d * 4 + lane] : 0.f;

    int p0 = off[d], p1 = off[d + 1];
    float4 acc = make_float4(0.f, 0.f, 0.f, 0.f);
    float den = 0.f;

    const float4* ft4 = reinterpret_cast<const float4*>(ft);
    for (int p = p0; p < p1; ++p) {
        int s = __ldg(&eidx[p]);
        float a = 0.f;
        if (lane < 4) {
            float v = el[(size_t)s * 4 + lane] + erv;
            v = (v > 0.f) ? v : SLOPE * v;
            a = __expf(v);
            den += a;
        }
        float ah = __shfl_sync(0xffffffffu, a, lane >> 3);   // head = lane/8
        float4 f = ft4[(size_t)s * 32 + lane];
        acc.x += ah * f.x;
        acc.y += ah * f.y;
        acc.z += ah * f.z;
        acc.w += ah * f.w;
    }

    float inv  = 1.0f / fmaxf(den, 1e-9f);                   // valid in lanes 0..3
    float invh = __shfl_sync(0xffffffffu, inv, lane >> 3);
    float4 r;
    r.x = elu1(acc.x * invh);
    r.y = elu1(acc.y * invh);
    r.z = elu1(acc.z * invh);
    r.w = elu1(acc.w * invh);
    reinterpret_cast<float4*>(out)[(size_t)d * 32 + lane] = r;
}

// =================================================================================
// Edge features: out[p, h*64 + 0..31] = hf[i0,h,:], [32..63] = hf[i1,h,:]
// =================================================================================
__global__ void gat_edgefeat_kernel(const float* __restrict__ hf,
                                    const int* __restrict__ ind0,
                                    const int* __restrict__ ind1,
                                    float* __restrict__ out)
{
    int idx = blockIdx.x * blockDim.x + threadIdx.x;
    if (idx >= EI * 64) return;
    int p = idx >> 6;
    int q = idx & 63;
    int h = q >> 4;
    int w = q & 15;
    int node = (w < 8) ? __ldg(&ind0[p]) : __ldg(&ind1[p]);
    float4 v = reinterpret_cast<const float4*>(hf)[(size_t)node * 32 + h * 8 + (w & 7)];
    reinterpret_cast<float4*>(out)[(size_t)p * 64 + q] = v;
}

// =================================================================================
// Launch
// =================================================================================
extern "C" void kernel_launch(void* const* d_in, const int* in_sizes, int n_in,
                              void* d_out, int out_size)
{
    const float* x      = (const float*)d_in[0];
    const int*   src    = (const int*)  d_in[1];
    const int*   dst    = (const int*)  d_in[2];
    const int*   indics = (const int*)  d_in[3];
    const float* W0     = (const float*)d_in[4];
    const float* al0    = (const float*)d_in[5];
    const float* ar0    = (const float*)d_in[6];
    const float* W1     = (const float*)d_in[7];
    const float* al1    = (const float*)d_in[8];
    const float* ar1    = (const float*)d_in[9];

    float* o     = (float*)d_out;
    float* h_out = o;                      // [N, 128]
    float* edges = o + (size_t)NN * 128;   // [E_IND, 256] (written LAST)

    float* ft  = o + S_FT;
    float* h1  = o + S_H1;
    float* el  = o + S_EL;
    float* er  = o + S_ER;
    int*   off = (int*)(o + S_OFF);
    int*   cur = (int*)(o + S_CUR);
    int*   eid = (int*)(o + S_EIDX);

    const int gemm_smem = (16384 + 128 * XPAD) * 4;    // 133,120 B
    static int attr_done = 0;
    if (!attr_done) {
        cudaFuncSetAttribute(gat_gemm_kernel,
                             cudaFuncAttributeMaxDynamicSharedMemorySize, gemm_smem);
        attr_done = 1;
    }

    const int gemm_grid = (NN + 127) / 128;            // 391
    const int edge_grid = (EE + 255) / 256;            // 3125
    const int agg_grid  = (NN * 32 + 255) / 256;       // 6250
    const int ef_grid   = (EI * 64 + 255) / 256;

    // ---- CSR build (graph is identical for both layers) ----
    cudaMemsetAsync(cur, 0, NN * sizeof(int));
    hist_kernel<<<edge_grid, 256>>>(dst, cur);
    scan_kernel<<<1, 1024>>>(cur, off);
    scatter_kernel<<<edge_grid, 256>>>(src, dst, cur, eid);

    // ---- layer 1 ----
    gat_gemm_kernel<<<gemm_grid, 512, gemm_smem>>>(x, W0, al0, ar0, ft, el, er);
    gat_aggregate_kernel<<<agg_grid, 256>>>(off, eid, ft, el, er, h1);

    // ---- layer 2 ----
    gat_gemm_kernel<<<gemm_grid, 512, gemm_smem>>>(h1, W1, al1, ar1, ft, el, er);
    gat_aggregate_kernel<<<agg_grid, 256>>>(off, eid, ft, el, er, h_out);

    // ---- edge features (overwrites scratch region last) ----
    gat_edgefeat_kernel<<<ef_grid, 256>>>(h_out, indics, indics + EI, edges);
}